// round 15
// baseline (speedup 1.0000x reference)
#include <cuda_runtime.h>
#include <cuda_fp16.h>
#include <cstdint>

#define Bb   4
#define Ss   2048
#define Dd   512
#define Hh   8
#define DKk  64
#define FFNf 2048
#define ROWS (Bb*Ss)   // 8192
#define GP   80
#define PKB  (128*GP)              // packed blob bytes (10240)
#define PKH  (PKB/2)
#define GSTG (2*PKB)               // narrow gemm stage (A+B)
#define GEMM_SMEM (3*GSTG + 64)
#define MBOFF (3*GSTG)
#define WSTG (3*PKB)               // wide gemm stage (A + 2xB)
#define WGEMM_SMEM (3*WSTG + 64)
#define WMBOFF (3*WSTG)
#define KVP   72
#define KSTG  (64*KVP*2)
#define ASTGB (2*KSTG)
#define ATTN_SMEM (3*ASTGB + 64)
#define AMBOFF (3*ASTGB)
#define KVBLOB (64*KVP)
#define ONESF 0x3C003C00u

// ---------------- scratch ---------------------------------------------------------
__device__ float  g_h[ROWS*Dd];
__device__ __half g_h16pk[64*16*PKH];
__device__ __half g_q16[ROWS*Dd];
__device__ __half g_kpk[32*32*KVBLOB];
__device__ __half g_vpk[32*32*KVBLOB];
__device__ float  g_attn[ROWS*Dd];
__device__ __half g_o16pk[64*16*PKH];
__device__ __half g_f16pk[64*64*PKH];
__device__ float  g_r[ROWS*Dd];
__device__ __half g_wqkvpk[12*16*PKH];
__device__ __half g_w1pk[16*16*PKH];
__device__ __half g_w2pk[4*64*PKH];
__device__ float  g_bqkv[3*Dd];

__constant__ int c_chunk_order[16] = {4,5,6,7,8,9,10,11,12,13,14,3,15,2,1,0};

// ---------------- helpers ----------------------------------------------------------
__device__ __forceinline__ uint32_t smem_u32(const void* p) {
    uint32_t a;
    asm("{ .reg .u64 t; cvta.to.shared.u64 t, %1; cvt.u32.u64 %0, t; }" : "=r"(a) : "l"(p));
    return a;
}
#define CPBULK(dst, src, bytes, mbar) \
    asm volatile("cp.async.bulk.shared::cluster.global.mbarrier::complete_tx::bytes [%0], [%1], %2, [%3];" \
        :: "r"(dst), "l"(src), "r"(bytes), "r"(mbar) : "memory")
#define MBAR_INIT(a, c) asm volatile("mbarrier.init.shared.b64 [%0], %1;" :: "r"(a), "r"(c) : "memory")
#define MBAR_EXPECT(a, b) asm volatile("mbarrier.arrive.expect_tx.shared.b64 _, [%0], %1;" :: "r"(a), "r"(b) : "memory")
#define MBAR_ARRIVE(a)  asm volatile("mbarrier.arrive.shared.b64 _, [%0];" :: "r"(a) : "memory")
#define MBAR_WAIT(a, ph) do {                                                              \
    uint32_t _m = (a), _p = (ph), _d;                                                      \
    asm volatile("{ .reg .pred p; mbarrier.try_wait.parity.acquire.cta.shared::cta.b64 p, [%1], %2; selp.b32 %0,1,0,p; }" \
        : "=r"(_d) : "r"(_m), "r"(_p) : "memory");                                         \
    if (!_d) {                                                                             \
        asm volatile("{ .reg .pred P1; WL_%=:\n\t"                                         \
            "mbarrier.try_wait.parity.acquire.cta.shared::cta.b64 P1, [%0], %1, 0x989680;\n\t" \
            "@P1 bra.uni WD_%=;\n\t bra.uni WL_%=;\n\t WD_%=: }"                           \
            :: "r"(_m), "r"(_p) : "memory");                                               \
    }                                                                                      \
} while (0)
#define FENCE_ASYNC()   asm volatile("fence.proxy.async.shared::cta;" ::: "memory")
#define LDSM4(r0,r1,r2,r3,a) \
    asm volatile("ldmatrix.sync.aligned.m8n8.x4.shared.b16 {%0,%1,%2,%3}, [%4];" \
        : "=r"(r0),"=r"(r1),"=r"(r2),"=r"(r3) : "r"(a))
#define LDSM4T(r0,r1,r2,r3,a) \
    asm volatile("ldmatrix.sync.aligned.m8n8.x4.trans.shared.b16 {%0,%1,%2,%3}, [%4];" \
        : "=r"(r0),"=r"(r1),"=r"(r2),"=r"(r3) : "r"(a))
#define EX2H2(d, a) asm("ex2.approx.f16x2 %0, %1;" : "=r"(d) : "r"(a))

__device__ __forceinline__ void mma16(float4& d,
                                      uint32_t a0, uint32_t a1, uint32_t a2, uint32_t a3,
                                      uint32_t b0, uint32_t b1) {
    asm volatile(
        "mma.sync.aligned.m16n8k16.row.col.f32.f16.f16.f32 "
        "{%0,%1,%2,%3}, {%4,%5,%6,%7}, {%8,%9}, {%0,%1,%2,%3};"
        : "+f"(d.x), "+f"(d.y), "+f"(d.z), "+f"(d.w)
        : "r"(a0), "r"(a1), "r"(a2), "r"(a3), "r"(b0), "r"(b1));
}

__device__ __forceinline__ size_t pk_off(int row, int k, int Ktiles) {
    return ((size_t)(row >> 7) * Ktiles + (k >> 5)) * PKH + (row & 127) * 40 + (k & 31);
}

// ---------------- LayerNorm (float4, 2 rows per CTA) ---------------------------------
__global__ __launch_bounds__(256) void ln_kernel(const float* __restrict__ x,
                                                 const float* __restrict__ gam,
                                                 const float* __restrict__ bet,
                                                 float* __restrict__ out32,
                                                 __half* __restrict__ out16pk)
{
    const int half = threadIdx.x >> 7;
    const int row  = blockIdx.x * 2 + half;
    const int t    = threadIdx.x & 127;
    const float4 v = ((const float4*)(x + (size_t)row * Dd))[t];
    float s  = v.x + v.y + v.z + v.w;
    float ss = v.x * v.x + v.y * v.y + v.z * v.z + v.w * v.w;
    #pragma unroll
    for (int o = 16; o; o >>= 1) {
        s  += __shfl_xor_sync(~0u, s,  o);
        ss += __shfl_xor_sync(~0u, ss, o);
    }
    __shared__ float rs[2][4], rss[2][4];
    const int wir = (threadIdx.x >> 5) & 3;
    if ((t & 31) == 0) { rs[half][wir] = s; rss[half][wir] = ss; }
    __syncthreads();
    float tot = 0.f, tot2 = 0.f;
    #pragma unroll
    for (int i = 0; i < 4; i++) { tot += rs[half][i]; tot2 += rss[half][i]; }
    const float mean = tot * (1.0f / Dd);
    const float var  = tot2 * (1.0f / Dd) - mean * mean;
    const float rstd = rsqrtf(var + 1e-5f);
    const float4 g4 = ((const float4*)gam)[t];
    const float4 b4 = ((const float4*)bet)[t];
    float4 o;
    o.x = (v.x - mean) * rstd * g4.x + b4.x;
    o.y = (v.y - mean) * rstd * g4.y + b4.y;
    o.z = (v.z - mean) * rstd * g4.z + b4.z;
    o.w = (v.w - mean) * rstd * g4.w + b4.w;
    if (out32) ((float4*)(out32 + (size_t)row * Dd))[t] = o;
    if (out16pk) {
        const int k = t * 4;
        __half2* dst = (__half2*)&out16pk[pk_off(row, k, Dd / 32)];
        dst[0] = __floats2half2_rn(o.x, o.y);
        dst[1] = __floats2half2_rn(o.z, o.w);
    }
}

// ---------------- merged prep --------------------------------------------------------
__global__ __launch_bounds__(256) void prep_kernel(
    const float* __restrict__ wq, const float* __restrict__ wk, const float* __restrict__ wv,
    const float* __restrict__ w1, const float* __restrict__ w2,
    const float* __restrict__ bq, const float* __restrict__ bk, const float* __restrict__ bv,
    __half* __restrict__ wqkvpk, __half* __restrict__ w1pk, __half* __restrict__ w2pk,
    float* __restrict__ bqkv)
{
    const int b = blockIdx.x;
    const int tid = threadIdx.x;
    if (b >= 2816) {
        const int i = (b - 2816) * 256 + tid;
        if (i < 512) bqkv[i] = bq[i];
        else if (i < 1024) bqkv[i] = bk[i - 512];
        else if (i < 1536) bqkv[i] = bv[i - 1024];
        return;
    }
    const float* W; __half* Wt; int K, N, n0, k0, noff;
    if (b < 768) {
        const int which = b >> 8, t = b & 255;
        W = which == 0 ? wq : (which == 1 ? wk : wv);
        Wt = wqkvpk; noff = which * Dd;
        K = Dd; N = Dd;
        n0 = (t & 15) * 32; k0 = (t >> 4) * 32;
    } else if (b < 1792) {
        const int t = b - 768;
        W = w1; Wt = w1pk; noff = 0; K = Dd; N = FFNf;
        n0 = (t & 63) * 32; k0 = (t >> 6) * 32;
    } else {
        const int t = b - 1792;
        W = w2; Wt = w2pk; noff = 0; K = FFNf; N = Dd;
        n0 = (t & 15) * 32; k0 = (t >> 4) * 32;
    }
    __shared__ float t[32][33];
    const int tx = tid & 31, ty = tid >> 5;
    #pragma unroll
    for (int i = 0; i < 32; i += 8) t[ty + i][tx] = W[(size_t)(k0 + ty + i) * N + n0 + tx];
    __syncthreads();
    const int Kt = K >> 5;
    #pragma unroll
    for (int i = 0; i < 32; i += 8) {
        const int n = noff + n0 + ty + i;
        const int k = k0 + tx;
        Wt[pk_off(n, k, Kt)] = __float2half_rn(t[tx][ty + i]);
    }
}

// ---------------- WIDE fp16 GEMM: 128x256 CTA, 512 thr, bulk-copy pipeline -----------
// MODE 0: fp16 PACKED out    MODE 1: Q normal + K/V packed blobs
template<int MODE>
__global__ __launch_bounds__(512, 1) void mma_gemm_w(const __half* __restrict__ Apk,
                                                     const __half* __restrict__ Bpk,
                                                     const float* __restrict__ bias,
                                                     float* __restrict__ C,
                                                     __half* __restrict__ C16,
                                                     __half* __restrict__ Kpk,
                                                     __half* __restrict__ Vpk,
                                                     int M, int N, int K)
{
    extern __shared__ __align__(16) char dyn[];

    const int tid  = threadIdx.x;
    const int m0   = blockIdx.y * 128;
    const int n0   = blockIdx.x * 256;
    const int w    = tid >> 5, lane = tid & 31;
    const int wm   = (w & 3) * 32;
    const int wn   = (w >> 2) * 64;
    const int r    = lane >> 2;
    const int c    = lane & 3;
    const int g    = lane >> 3, lr = lane & 7;

    float4 acc[2][8];
    #pragma unroll
    for (int i = 0; i < 2; i++)
        #pragma unroll
        for (int j = 0; j < 8; j++) acc[i][j] = make_float4(0.f, 0.f, 0.f, 0.f);

    const uint32_t sbase = smem_u32(dyn);
    const uint32_t fullb = sbase + WMBOFF;
    const uint32_t mtyb  = sbase + WMBOFF + 24;
    const int T = K >> 5;
    const char* Asrc  = (const char*)Apk + (size_t)(m0 >> 7) * T * PKB;
    const char* Bsrc0 = (const char*)Bpk + (size_t)(n0 >> 7) * T * PKB;
    const char* Bsrc1 = Bsrc0 + (size_t)T * PKB;

    const uint32_t aoff = (uint32_t)((wm + (g & 1) * 8 + lr) * GP + (g >> 1) * 16);
    // B rows local to 128-row blob: wn<128 -> blob0; wn>=128 -> blob1 (+PKB)
    const uint32_t bblob = (wn >> 7) ? (uint32_t)(PKB + PKB) : (uint32_t)PKB;  // offset of B half from stage base
    const int wnl = wn & 127;
    const uint32_t boff = bblob + (uint32_t)((wnl + ((g >> 1) & 1) * 8 + lr) * GP + (g & 1) * 16);

    if (tid == 0) {
        MBAR_INIT(fullb, 1); MBAR_INIT(fullb + 8, 1); MBAR_INIT(fullb + 16, 1);
        MBAR_INIT(mtyb, 16); MBAR_INIT(mtyb + 8, 16); MBAR_INIT(mtyb + 16, 16);
        FENCE_ASYNC();
    }
    __syncthreads();
    if (tid == 0) {
        #pragma unroll
        for (int p = 0; p < 2; p++) {
            MBAR_EXPECT(fullb + p * 8, WSTG);
            CPBULK(sbase + p * WSTG,           Asrc  + (size_t)p * PKB, PKB, fullb + p * 8);
            CPBULK(sbase + p * WSTG + PKB,     Bsrc0 + (size_t)p * PKB, PKB, fullb + p * 8);
            CPBULK(sbase + p * WSTG + 2 * PKB, Bsrc1 + (size_t)p * PKB, PKB, fullb + p * 8);
        }
    }

    for (int t = 0; t < T; t++) {
        const int s = t % 3;
        if (tid == 0 && t + 2 < T) {
            const int u = t + 2, l = u % 3;
            if (u >= 3) MBAR_WAIT(mtyb + l * 8, (uint32_t)((u / 3 - 1) & 1));
            MBAR_EXPECT(fullb + l * 8, WSTG);
            CPBULK(sbase + l * WSTG,           Asrc  + (size_t)u * PKB, PKB, fullb + l * 8);
            CPBULK(sbase + l * WSTG + PKB,     Bsrc0 + (size_t)u * PKB, PKB, fullb + l * 8);
            CPBULK(sbase + l * WSTG + 2 * PKB, Bsrc1 + (size_t)u * PKB, PKB, fullb + l * 8);
        }
        MBAR_WAIT(fullb + s * 8, (uint32_t)((t / 3) & 1));

        const uint32_t sAb = sbase + s * WSTG;
        #pragma unroll
        for (int kg = 0; kg < 2; kg++) {
            uint32_t af[2][4];
            #pragma unroll
            for (int mt = 0; mt < 2; mt++)
                LDSM4(af[mt][0], af[mt][1], af[mt][2], af[mt][3],
                      sAb + aoff + (uint32_t)(mt * 16 * GP + kg * 32));
            uint32_t bf[4][4];
            #pragma unroll
            for (int nt2 = 0; nt2 < 4; nt2++)
                LDSM4(bf[nt2][0], bf[nt2][1], bf[nt2][2], bf[nt2][3],
                      sAb + boff + (uint32_t)(nt2 * 16 * GP + kg * 32));
            #pragma unroll
            for (int mt = 0; mt < 2; mt++) {
                #pragma unroll
                for (int nt2 = 0; nt2 < 4; nt2++) {
                    mma16(acc[mt][nt2 * 2],     af[mt][0], af[mt][1], af[mt][2], af[mt][3],
                          bf[nt2][0], bf[nt2][1]);
                    mma16(acc[mt][nt2 * 2 + 1], af[mt][0], af[mt][1], af[mt][2], af[mt][3],
                          bf[nt2][2], bf[nt2][3]);
                }
            }
        }
        if (lane == 0) MBAR_ARRIVE(mtyb + s * 8);
    }

    #pragma unroll
    for (int mt = 0; mt < 2; mt++) {
        #pragma unroll
        for (int nt = 0; nt < 8; nt++) {
            const int m = m0 + wm + mt * 16 + r;
            const int n = n0 + wn + nt * 8 + c * 2;
            const float2 bv = *(const float2*)&bias[n];
            float2 lo, hi;
            lo.x = acc[mt][nt].x + bv.x;  lo.y = acc[mt][nt].y + bv.y;
            hi.x = acc[mt][nt].z + bv.x;  hi.y = acc[mt][nt].w + bv.y;
            if (MODE == 1) {
                const int which = n >> 9;
                const int nn = n & 511;
                const int hh = nn >> 6, d = nn & 63;
                const int b0i = m >> 11, s0 = m & (Ss - 1);
                const int b1i = (m + 8) >> 11, s1 = (m + 8) & (Ss - 1);
                if (which == 0) {
                    *(__half2*)&C16[((((size_t)b0i * Hh + hh) * Ss) + s0) * DKk + d] =
                        __floats2half2_rn(lo.x, lo.y);
                    *(__half2*)&C16[((((size_t)b1i * Hh + hh) * Ss) + s1) * DKk + d] =
                        __floats2half2_rn(hi.x, hi.y);
                } else {
                    __half* dst = (which == 1) ? Kpk : Vpk;
                    const size_t o0 = ((size_t)(b0i * Hh + hh) * 32 + (s0 >> 6)) * KVBLOB
                                    + (s0 & 63) * KVP + d;
                    const size_t o1 = ((size_t)(b1i * Hh + hh) * 32 + (s1 >> 6)) * KVBLOB
                                    + (s1 & 63) * KVP + d;
                    *(__half2*)&dst[o0] = __floats2half2_rn(lo.x, lo.y);
                    *(__half2*)&dst[o1] = __floats2half2_rn(hi.x, hi.y);
                }
            } else {
                const int kt = N >> 5;
                *(__half2*)&C16[pk_off(m,     n, kt)] = __floats2half2_rn(lo.x, lo.y);
                *(__half2*)&C16[pk_off(m + 8, n, kt)] = __floats2half2_rn(hi.x, hi.y);
            }
        }
    }
}

// ---------------- narrow fp16 GEMM (FFN2): 128x128, fp32 +res ------------------------
__global__ __launch_bounds__(256, 2) void mma_gemm_n(const __half* __restrict__ Apk,
                                                     const __half* __restrict__ Bpk,
                                                     const float* __restrict__ bias,
                                                     const float* __restrict__ res,
                                                     float* __restrict__ C,
                                                     int M, int N, int K)
{
    extern __shared__ __align__(16) char dyn[];

    const int tid  = threadIdx.x;
    const int m0   = blockIdx.y * 128;
    const int n0   = blockIdx.x * 128;
    const int w    = tid >> 5, lane = tid & 31;
    const int wm   = (w & 1) * 64;
    const int wn   = (w >> 1) * 32;
    const int r    = lane >> 2;
    const int c    = lane & 3;
    const int g    = lane >> 3, lr = lane & 7;

    float4 acc[4][4];
    #pragma unroll
    for (int i = 0; i < 4; i++)
        #pragma unroll
        for (int j = 0; j < 4; j++) acc[i][j] = make_float4(0.f, 0.f, 0.f, 0.f);

    const uint32_t sbase = smem_u32(dyn);
    const uint32_t fullb = sbase + MBOFF;
    const uint32_t mtyb  = sbase + MBOFF + 24;
    const int T = K >> 5;
    const char* Asrc = (const char*)Apk + (size_t)(m0 >> 7) * T * PKB;
    const char* Bsrc = (const char*)Bpk + (size_t)(n0 >> 7) * T * PKB;

    const uint32_t aoff = (uint32_t)((wm + (g & 1) * 8 + lr) * GP + (g >> 1) * 16);
    const uint32_t boff = (uint32_t)((wn + ((g >> 1) & 1) * 8 + lr) * GP + (g & 1) * 16);

    if (tid == 0) {
        MBAR_INIT(fullb, 1); MBAR_INIT(fullb + 8, 1); MBAR_INIT(fullb + 16, 1);
        MBAR_INIT(mtyb, 8);  MBAR_INIT(mtyb + 8, 8);  MBAR_INIT(mtyb + 16, 8);
        FENCE_ASYNC();
    }
    __syncthreads();
    if (tid == 0) {
        #pragma unroll
        for (int p = 0; p < 2; p++) {
            MBAR_EXPECT(fullb + p * 8, GSTG);
            CPBULK(sbase + p * GSTG,       Asrc + (size_t)p * PKB, PKB, fullb + p * 8);
            CPBULK(sbase + p * GSTG + PKB, Bsrc + (size_t)p * PKB, PKB, fullb + p * 8);
        }
    }

    for (int t = 0; t < T; t++) {
        const int s = t % 3;
        if (tid == 0 && t + 2 < T) {
            const int u = t + 2, l = u % 3;
            if (u >= 3) MBAR_WAIT(mtyb + l * 8, (uint32_t)((u / 3 - 1) & 1));
            MBAR_EXPECT(fullb + l * 8, GSTG);
            CPBULK(sbase + l * GSTG,       Asrc + (size_t)u * PKB, PKB, fullb + l * 8);
            CPBULK(sbase + l * GSTG + PKB, Bsrc + (size_t)u * PKB, PKB, fullb + l * 8);
        }
        MBAR_WAIT(fullb + s * 8, (uint32_t)((t / 3) & 1));

        const uint32_t sAb = sbase + s * GSTG;
        const uint32_t sBb = sAb + PKB;
        #pragma unroll
        for (int kg = 0; kg < 2; kg++) {
            uint32_t af[4][4];
            #pragma unroll
            for (int mt = 0; mt < 4; mt++)
                LDSM4(af[mt][0], af[mt][1], af[mt][2], af[mt][3],
                      sAb + aoff + (uint32_t)(mt * 16 * GP + kg * 32));
            uint32_t bf[2][4];
            #pragma unroll
            for (int nt2 = 0; nt2 < 2; nt2++)
                LDSM4(bf[nt2][0], bf[nt2][1], bf[nt2][2], bf[nt2][3],
                      sBb + boff + (uint32_t)(nt2 * 16 * GP + kg * 32));
            #pragma unroll
            for (int mt = 0; mt < 4; mt++) {
                #pragma unroll
                for (int nt2 = 0; nt2 < 2; nt2++) {
                    mma16(acc[mt][nt2 * 2],     af[mt][0], af[mt][1], af[mt][2], af[mt][3],
                          bf[nt2][0], bf[nt2][1]);
                    mma16(acc[mt][nt2 * 2 + 1], af[mt][0], af[mt][1], af[mt][2], af[mt][3],
                          bf[nt2][2], bf[nt2][3]);
                }
            }
        }
        if (lane == 0) MBAR_ARRIVE(mtyb + s * 8);
    }

    #pragma unroll
    for (int mt = 0; mt < 4; mt++) {
        #pragma unroll
        for (int nt = 0; nt < 4; nt++) {
            const int m = m0 + wm + mt * 16 + r;
            const int n = n0 + wn + nt * 8 + c * 2;
            const float2 bv = *(const float2*)&bias[n];
            const float2 r0 = *(const float2*)&res[(size_t)m * N + n];
            const float2 r1 = *(const float2*)&res[(size_t)(m + 8) * N + n];
            float2 lo, hi;
            lo.x = acc[mt][nt].x + bv.x + r0.x;  lo.y = acc[mt][nt].y + bv.y + r0.y;
            hi.x = acc[mt][nt].z + bv.x + r1.x;  hi.y = acc[mt][nt].w + bv.y + r1.y;
            *(float2*)&C[(size_t)m * N + n]       = lo;
            *(float2*)&C[(size_t)(m + 8) * N + n] = hi;
        }
    }
}

// ---------------- MMA flash attention (unchanged from R14) ---------------------------
__global__ __launch_bounds__(256, 2) void attn_mma(const __half* __restrict__ qh,
                                                   const __half* __restrict__ kpk,
                                                   const __half* __restrict__ vpk,
                                                   const float* __restrict__ hin,
                                                   float* __restrict__ out)
{
    extern __shared__ __align__(16) char dyn[];

    const int bx  = blockIdx.x;
    const int bh  = bx >> 4;
    const int cs  = c_chunk_order[bx & 15] * 128;
    const int tid = threadIdx.x;
    const int w = tid >> 5, lane = tid & 31;
    const int r = lane >> 2;
    const int c = lane & 3;
    const size_t bhS = (size_t)bh * Ss;

    uint32_t qf[4][4];
    {
        const int q0 = cs + w * 16;
        const __half2 scl = __half2half2(__float2half(0.125f * 1.44269504f));
        #pragma unroll
        for (int ks = 0; ks < 4; ks++) {
            const __half* qp0 = qh + (bhS + q0 + r) * DKk + ks * 16 + c * 2;
            const __half* qp1 = qp0 + 8 * DKk;
            __half2 a0 = __hmul2(*(const __half2*)qp0, scl);
            __half2 a1 = __hmul2(*(const __half2*)qp1, scl);
            __half2 a2 = __hmul2(*(const __half2*)(qp0 + 8), scl);
            __half2 a3 = __hmul2(*(const __half2*)(qp1 + 8), scl);
            qf[ks][0] = *(uint32_t*)&a0; qf[ks][1] = *(uint32_t*)&a1;
            qf[ks][2] = *(uint32_t*)&a2; qf[ks][3] = *(uint32_t*)&a3;
        }
    }

    const uint32_t sbase = smem_u32(dyn);
    const uint32_t fullb = sbase + AMBOFF;
    const uint32_t mtyb  = sbase + AMBOFF + 24;

    int w0 = cs - 512; if (w0 < 0) w0 = 0;
    int w1 = cs + 256; if (w1 > Ss) w1 = Ss;
    const int T = (w1 - w0) >> 6;
    const int t0 = w0 >> 6;
    const char* Kb = (const char*)(kpk + (size_t)bh * 32 * KVBLOB);
    const char* Vb = (const char*)(vpk + (size_t)bh * 32 * KVBLOB);

    if (tid == 0) {
        MBAR_INIT(fullb, 1); MBAR_INIT(fullb + 8, 1); MBAR_INIT(fullb + 16, 1);
        MBAR_INIT(mtyb, 8);  MBAR_INIT(mtyb + 8, 8);  MBAR_INIT(mtyb + 16, 8);
        FENCE_ASYNC();
    }
    __syncthreads();
    if (tid == 0) {
        #pragma unroll
        for (int p = 0; p < 2; p++) {
            if (p < T) {
                MBAR_EXPECT(fullb + p * 8, ASTGB);
                CPBULK(sbase + p * ASTGB,        Kb + (size_t)(t0 + p) * KSTG, KSTG, fullb + p * 8);
                CPBULK(sbase + p * ASTGB + KSTG, Vb + (size_t)(t0 + p) * KSTG, KSTG, fullb + p * 8);
            }
        }
    }

    float4 lacc = make_float4(0.f, 0.f, 0.f, 0.f);
    float4 accO[8];
    #pragma unroll
    for (int i = 0; i < 8; i++) accO[i] = make_float4(0.f, 0.f, 0.f, 0.f);

    const int qk_row = (lane & 7) + ((lane >> 4) & 1) * 8;
    const int qk_col = ((lane >> 3) & 1) * 8;
    const int pv_row = (lane & 7) + ((lane >> 3) & 1) * 8;
    const int pv_col = ((lane >> 4) & 1) * 8;

    for (int t = 0; t < T; t++) {
        const int s = t % 3;
        if (tid == 0 && t + 2 < T) {
            const int u = t + 2, l = u % 3;
            if (u >= 3) MBAR_WAIT(mtyb + l * 8, (uint32_t)((u / 3 - 1) & 1));
            MBAR_EXPECT(fullb + l * 8, ASTGB);
            CPBULK(sbase + l * ASTGB,        Kb + (size_t)(t0 + u) * KSTG, KSTG, fullb + l * 8);
            CPBULK(sbase + l * ASTGB + KSTG, Vb + (size_t)(t0 + u) * KSTG, KSTG, fullb + l * 8);
        }
        MBAR_WAIT(fullb + s * 8, (uint32_t)((t / 3) & 1));

        const uint32_t sKb = sbase + s * ASTGB;
        const uint32_t sVb = sKb + KSTG;

        float4 sc[8];
        #pragma unroll
        for (int i = 0; i < 8; i++) sc[i] = make_float4(0.f, 0.f, 0.f, 0.f);
        #pragma unroll
        for (int ks = 0; ks < 4; ks++) {
            #pragma unroll
            for (int n2 = 0; n2 < 4; n2++) {
                uint32_t b0, b1, b2, b3;
                const uint32_t a = sKb +
                    (uint32_t)((n2 * 16 + qk_row) * KVP + ks * 16 + qk_col) * 2;
                LDSM4(b0, b1, b2, b3, a);
                mma16(sc[2 * n2],     qf[ks][0], qf[ks][1], qf[ks][2], qf[ks][3], b0, b1);
                mma16(sc[2 * n2 + 1], qf[ks][0], qf[ks][1], qf[ks][2], qf[ks][3], b2, b3);
            }
        }

        uint32_t pf[4][4];
        #pragma unroll
        for (int ks = 0; ks < 4; ks++) {
            __half2 h;
            uint32_t u0, u1, u2, u3;
            h = __floats2half2_rn(sc[2 * ks].x,     sc[2 * ks].y);     u0 = *(uint32_t*)&h;
            h = __floats2half2_rn(sc[2 * ks].z,     sc[2 * ks].w);     u1 = *(uint32_t*)&h;
            h = __floats2half2_rn(sc[2 * ks + 1].x, sc[2 * ks + 1].y); u2 = *(uint32_t*)&h;
            h = __floats2half2_rn(sc[2 * ks + 1].z, sc[2 * ks + 1].w); u3 = *(uint32_t*)&h;
            EX2H2(pf[ks][0], u0);
            EX2H2(pf[ks][1], u1);
            EX2H2(pf[ks][2], u2);
            EX2H2(pf[ks][3], u3);
        }

        #pragma unroll
        for (int ks = 0; ks < 4; ks++)
            mma16(lacc, pf[ks][0], pf[ks][1], pf[ks][2], pf[ks][3], ONESF, ONESF);

        #pragma unroll
        for (int ks = 0; ks < 4; ks++) {
            #pragma unroll
            for (int d2 = 0; d2 < 4; d2++) {
                uint32_t b0, b1, b2, b3;
                const uint32_t a = sVb +
                    (uint32_t)((ks * 16 + pv_row) * KVP + d2 * 16 + pv_col) * 2;
                LDSM4T(b0, b1, b2, b3, a);
                mma16(accO[2 * d2],     pf[ks][0], pf[ks][1], pf[ks][2], pf[ks][3], b0, b1);
                mma16(accO[2 * d2 + 1], pf[ks][0], pf[ks][1], pf[ks][2], pf[ks][3], b2, b3);
            }
        }
        if (lane == 0) MBAR_ARRIVE(mtyb + s * 8);
    }

    const float inv0 = 1.0f / lacc.x;
    const float inv1 = 1.0f / lacc.z;
    const int b = bh >> 3, head = bh & 7;
    const int q0 = cs + w * 16;
    const size_t base0 = ((size_t)b * Ss + q0 + r) * Dd + head * DKk;
    const size_t base1 = base0 + 8 * Dd;
    #pragma unroll
    for (int dn = 0; dn < 8; dn++) {
        const int d = dn * 8 + c * 2;
        const float2 h0 = *(const float2*)&hin[base0 + d];
        const float2 h1 = *(const float2*)&hin[base1 + d];
        float2 o0, o1;
        o0.x = accO[dn].x * inv0 + h0.x;  o0.y = accO[dn].y * inv0 + h0.y;
        o1.x = accO[dn].z * inv1 + h1.x;  o1.y = accO[dn].w * inv1 + h1.y;
        *(float2*)&out[base0 + d] = o0;
        *(float2*)&out[base1 + d] = o1;
    }
}

// ---------------- launch --------------------------------------------------------------
extern "C" void kernel_launch(void* const* d_in, const int* in_sizes, int n_in,
                              void* d_out, int out_size)
{
    const float* x       = (const float*)d_in[0];
    const float* ln_in_g = (const float*)d_in[2];
    const float* ln_in_b = (const float*)d_in[3];
    const float* wq = (const float*)d_in[4];  const float* bq = (const float*)d_in[5];
    const float* wk = (const float*)d_in[6];  const float* bk = (const float*)d_in[7];
    const float* wv = (const float*)d_in[8];  const float* bv = (const float*)d_in[9];
    const float* ln1_g = (const float*)d_in[10]; const float* ln1_b = (const float*)d_in[11];
    const float* w1 = (const float*)d_in[12]; const float* b1 = (const float*)d_in[13];
    const float* w2 = (const float*)d_in[14]; const float* b2 = (const float*)d_in[15];
    const float* ln2_g = (const float*)d_in[16]; const float* ln2_b = (const float*)d_in[17];
    float* out = (float*)d_out;

    float *ph, *pattn, *pr, *pbqkv;
    __half *ph16, *pq16, *pkpk, *pvpk, *po16, *pf16, *pwqkv, *pw1, *pw2;
    cudaGetSymbolAddress((void**)&ph,     g_h);
    cudaGetSymbolAddress((void**)&ph16,   g_h16pk);
    cudaGetSymbolAddress((void**)&pq16,   g_q16);
    cudaGetSymbolAddress((void**)&pkpk,   g_kpk);
    cudaGetSymbolAddress((void**)&pvpk,   g_vpk);
    cudaGetSymbolAddress((void**)&pattn,  g_attn);
    cudaGetSymbolAddress((void**)&po16,   g_o16pk);
    cudaGetSymbolAddress((void**)&pf16,   g_f16pk);
    cudaGetSymbolAddress((void**)&pr,     g_r);
    cudaGetSymbolAddress((void**)&pwqkv,  g_wqkvpk);
    cudaGetSymbolAddress((void**)&pw1,    g_w1pk);
    cudaGetSymbolAddress((void**)&pw2,    g_w2pk);
    cudaGetSymbolAddress((void**)&pbqkv,  g_bqkv);

    cudaFuncSetAttribute(mma_gemm_w<0>, cudaFuncAttributeMaxDynamicSharedMemorySize, WGEMM_SMEM);
    cudaFuncSetAttribute(mma_gemm_w<1>, cudaFuncAttributeMaxDynamicSharedMemorySize, WGEMM_SMEM);
    cudaFuncSetAttribute(mma_gemm_n,    cudaFuncAttributeMaxDynamicSharedMemorySize, GEMM_SMEM);
    cudaFuncSetAttribute(attn_mma,      cudaFuncAttributeMaxDynamicSharedMemorySize, ATTN_SMEM);

    // 0. merged prep -> packed weights
    prep_kernel<<<2822, 256>>>(wq, wk, wv, w1, w2, bq, bk, bv,
                               pwqkv, pw1, pw2, pbqkv);

    // 1. h = LN(x)
    ln_kernel<<<ROWS / 2, 256>>>(x, ln_in_g, ln_in_b, ph, ph16);

    // 2. fused QKV (wide tiles)
    mma_gemm_w<1><<<dim3(6, 64), 512, WGEMM_SMEM>>>(ph16, pwqkv, pbqkv, nullptr,
                                                    pq16, pkpk, pvpk, ROWS, 3 * Dd, Dd);

    // 3. attention + residual h
    attn_mma<<<512, 256, ATTN_SMEM>>>(pq16, pkpk, pvpk, ph, pattn);

    // 4. LN1 -> packed fp16
    ln_kernel<<<ROWS / 2, 256>>>(pattn, ln1_g, ln1_b, nullptr, po16);

    // 5. FFN1 wide, FFN2 narrow (+res)
    mma_gemm_w<0><<<dim3(FFNf / 256, 64), 512, WGEMM_SMEM>>>(po16, pw1, b1, nullptr,
                                                             pf16, nullptr, nullptr,
                                                             ROWS, FFNf, Dd);
    mma_gemm_n<<<dim3(Dd / 128, 64), 256, GEMM_SMEM>>>(pf16, pw2, b2, pattn, pr,
                                                       ROWS, Dd, FFNf);

    // 6. out = LN2
    ln_kernel<<<ROWS / 2, 256>>>(pr, ln2_g, ln2_b, out, nullptr);
}

// round 16
// speedup vs baseline: 1.1468x; 1.1468x over previous
#include <cuda_runtime.h>
#include <cuda_fp16.h>
#include <cstdint>

#define Bb   4
#define Ss   2048
#define Dd   512
#define Hh   8
#define DKk  64
#define FFNf 2048
#define ROWS (Bb*Ss)   // 8192
#define GP   80
#define PKB  (128*GP)              // packed blob bytes (10240)
#define PKH  (PKB/2)
#define GSTG (2*PKB)               // gemm stage bytes (A+B)
#define GNS  4                     // gemm pipeline stages
#define GEMM_SMEM (GNS*GSTG + 96)
#define MBOFF (GNS*GSTG)
#define KVP   72
#define KSTG  (64*KVP*2)
#define ASTGB (2*KSTG)
#define ATTN_SMEM (3*ASTGB + 64)
#define AMBOFF (3*ASTGB)
#define KVBLOB (64*KVP)
#define ONESF 0x3C003C00u

// ---------------- scratch ---------------------------------------------------------
__device__ float  g_h[ROWS*Dd];
__device__ __half g_h16pk[64*16*PKH];
__device__ __half g_q16[ROWS*Dd];
__device__ __half g_kpk[32*32*KVBLOB];
__device__ __half g_vpk[32*32*KVBLOB];
__device__ float  g_attn[ROWS*Dd];
__device__ __half g_o16pk[64*16*PKH];
__device__ __half g_f16pk[64*64*PKH];
__device__ float  g_r[ROWS*Dd];
__device__ __half g_wqkvpk[12*16*PKH];
__device__ __half g_w1pk[16*16*PKH];
__device__ __half g_w2pk[4*64*PKH];
__device__ float  g_bqkv[3*Dd];

__constant__ int c_chunk_order[16] = {4,5,6,7,8,9,10,11,12,13,14,3,15,2,1,0};

// ---------------- helpers ----------------------------------------------------------
__device__ __forceinline__ uint32_t smem_u32(const void* p) {
    uint32_t a;
    asm("{ .reg .u64 t; cvta.to.shared.u64 t, %1; cvt.u32.u64 %0, t; }" : "=r"(a) : "l"(p));
    return a;
}
#define CPBULK(dst, src, bytes, mbar) \
    asm volatile("cp.async.bulk.shared::cluster.global.mbarrier::complete_tx::bytes [%0], [%1], %2, [%3];" \
        :: "r"(dst), "l"(src), "r"(bytes), "r"(mbar) : "memory")
#define MBAR_INIT(a, c) asm volatile("mbarrier.init.shared.b64 [%0], %1;" :: "r"(a), "r"(c) : "memory")
#define MBAR_EXPECT(a, b) asm volatile("mbarrier.arrive.expect_tx.shared.b64 _, [%0], %1;" :: "r"(a), "r"(b) : "memory")
#define MBAR_ARRIVE(a)  asm volatile("mbarrier.arrive.shared.b64 _, [%0];" :: "r"(a) : "memory")
#define MBAR_WAIT(a, ph) do {                                                              \
    uint32_t _m = (a), _p = (ph), _d;                                                      \
    asm volatile("{ .reg .pred p; mbarrier.try_wait.parity.acquire.cta.shared::cta.b64 p, [%1], %2; selp.b32 %0,1,0,p; }" \
        : "=r"(_d) : "r"(_m), "r"(_p) : "memory");                                         \
    if (!_d) {                                                                             \
        asm volatile("{ .reg .pred P1; WL_%=:\n\t"                                         \
            "mbarrier.try_wait.parity.acquire.cta.shared::cta.b64 P1, [%0], %1, 0x989680;\n\t" \
            "@P1 bra.uni WD_%=;\n\t bra.uni WL_%=;\n\t WD_%=: }"                           \
            :: "r"(_m), "r"(_p) : "memory");                                               \
    }                                                                                      \
} while (0)
#define FENCE_ASYNC()   asm volatile("fence.proxy.async.shared::cta;" ::: "memory")
#define LDSM4(r0,r1,r2,r3,a) \
    asm volatile("ldmatrix.sync.aligned.m8n8.x4.shared.b16 {%0,%1,%2,%3}, [%4];" \
        : "=r"(r0),"=r"(r1),"=r"(r2),"=r"(r3) : "r"(a))
#define LDSM4T(r0,r1,r2,r3,a) \
    asm volatile("ldmatrix.sync.aligned.m8n8.x4.trans.shared.b16 {%0,%1,%2,%3}, [%4];" \
        : "=r"(r0),"=r"(r1),"=r"(r2),"=r"(r3) : "r"(a))
#define EX2H2(d, a) asm("ex2.approx.f16x2 %0, %1;" : "=r"(d) : "r"(a))

__device__ __forceinline__ void mma16(float4& d,
                                      uint32_t a0, uint32_t a1, uint32_t a2, uint32_t a3,
                                      uint32_t b0, uint32_t b1) {
    asm volatile(
        "mma.sync.aligned.m16n8k16.row.col.f32.f16.f16.f32 "
        "{%0,%1,%2,%3}, {%4,%5,%6,%7}, {%8,%9}, {%0,%1,%2,%3};"
        : "+f"(d.x), "+f"(d.y), "+f"(d.z), "+f"(d.w)
        : "r"(a0), "r"(a1), "r"(a2), "r"(a3), "r"(b0), "r"(b1));
}

__device__ __forceinline__ size_t pk_off(int row, int k, int Ktiles) {
    return ((size_t)(row >> 7) * Ktiles + (k >> 5)) * PKH + (row & 127) * 40 + (k & 31);
}

// ---------------- LayerNorm (float4, 2 rows per CTA) ---------------------------------
__global__ __launch_bounds__(256) void ln_kernel(const float* __restrict__ x,
                                                 const float* __restrict__ gam,
                                                 const float* __restrict__ bet,
                                                 float* __restrict__ out32,
                                                 __half* __restrict__ out16pk)
{
    const int half = threadIdx.x >> 7;
    const int row  = blockIdx.x * 2 + half;
    const int t    = threadIdx.x & 127;
    const float4 v = ((const float4*)(x + (size_t)row * Dd))[t];
    float s  = v.x + v.y + v.z + v.w;
    float ss = v.x * v.x + v.y * v.y + v.z * v.z + v.w * v.w;
    #pragma unroll
    for (int o = 16; o; o >>= 1) {
        s  += __shfl_xor_sync(~0u, s,  o);
        ss += __shfl_xor_sync(~0u, ss, o);
    }
    __shared__ float rs[2][4], rss[2][4];
    const int wir = (threadIdx.x >> 5) & 3;
    if ((t & 31) == 0) { rs[half][wir] = s; rss[half][wir] = ss; }
    __syncthreads();
    float tot = 0.f, tot2 = 0.f;
    #pragma unroll
    for (int i = 0; i < 4; i++) { tot += rs[half][i]; tot2 += rss[half][i]; }
    const float mean = tot * (1.0f / Dd);
    const float var  = tot2 * (1.0f / Dd) - mean * mean;
    const float rstd = rsqrtf(var + 1e-5f);
    const float4 g4 = ((const float4*)gam)[t];
    const float4 b4 = ((const float4*)bet)[t];
    float4 o;
    o.x = (v.x - mean) * rstd * g4.x + b4.x;
    o.y = (v.y - mean) * rstd * g4.y + b4.y;
    o.z = (v.z - mean) * rstd * g4.z + b4.z;
    o.w = (v.w - mean) * rstd * g4.w + b4.w;
    if (out32) ((float4*)(out32 + (size_t)row * Dd))[t] = o;
    if (out16pk) {
        const int k = t * 4;
        __half2* dst = (__half2*)&out16pk[pk_off(row, k, Dd / 32)];
        dst[0] = __floats2half2_rn(o.x, o.y);
        dst[1] = __floats2half2_rn(o.z, o.w);
    }
}

// ---------------- merged prep --------------------------------------------------------
__global__ __launch_bounds__(256) void prep_kernel(
    const float* __restrict__ wq, const float* __restrict__ wk, const float* __restrict__ wv,
    const float* __restrict__ w1, const float* __restrict__ w2,
    const float* __restrict__ bq, const float* __restrict__ bk, const float* __restrict__ bv,
    __half* __restrict__ wqkvpk, __half* __restrict__ w1pk, __half* __restrict__ w2pk,
    float* __restrict__ bqkv)
{
    const int b = blockIdx.x;
    const int tid = threadIdx.x;
    if (b >= 2816) {
        const int i = (b - 2816) * 256 + tid;
        if (i < 512) bqkv[i] = bq[i];
        else if (i < 1024) bqkv[i] = bk[i - 512];
        else if (i < 1536) bqkv[i] = bv[i - 1024];
        return;
    }
    const float* W; __half* Wt; int K, N, n0, k0, noff;
    if (b < 768) {
        const int which = b >> 8, t = b & 255;
        W = which == 0 ? wq : (which == 1 ? wk : wv);
        Wt = wqkvpk; noff = which * Dd;
        K = Dd; N = Dd;
        n0 = (t & 15) * 32; k0 = (t >> 4) * 32;
    } else if (b < 1792) {
        const int t = b - 768;
        W = w1; Wt = w1pk; noff = 0; K = Dd; N = FFNf;
        n0 = (t & 63) * 32; k0 = (t >> 6) * 32;
    } else {
        const int t = b - 1792;
        W = w2; Wt = w2pk; noff = 0; K = FFNf; N = Dd;
        n0 = (t & 15) * 32; k0 = (t >> 4) * 32;
    }
    __shared__ float t[32][33];
    const int tx = tid & 31, ty = tid >> 5;
    #pragma unroll
    for (int i = 0; i < 32; i += 8) t[ty + i][tx] = W[(size_t)(k0 + ty + i) * N + n0 + tx];
    __syncthreads();
    const int Kt = K >> 5;
    #pragma unroll
    for (int i = 0; i < 32; i += 8) {
        const int n = noff + n0 + ty + i;
        const int k = k0 + tx;
        Wt[pk_off(n, k, Kt)] = __float2half_rn(t[tx][ty + i]);
    }
}

// ---------------- fp16 warp-MMA GEMM: 4-stage bulk-copy pipeline ---------------------
// MODE 0: fp16 PACKED out  MODE 1: Q normal + K/V packed blobs  MODE 2: fp32 +res
template<int MODE>
__global__ __launch_bounds__(256, 2) void mma_gemm(const __half* __restrict__ Apk,
                                                   const __half* __restrict__ Bpk,
                                                   const float* __restrict__ bias,
                                                   const float* __restrict__ res,
                                                   float* __restrict__ C,
                                                   __half* __restrict__ C16,
                                                   __half* __restrict__ Kpk,
                                                   __half* __restrict__ Vpk,
                                                   int M, int N, int K)
{
    extern __shared__ __align__(16) char dyn[];

    const int tid  = threadIdx.x;
    const int m0   = blockIdx.y * 128;
    const int n0   = blockIdx.x * 128;
    const int w    = tid >> 5, lane = tid & 31;
    const int wm   = (w & 1) * 64;
    const int wn   = (w >> 1) * 32;
    const int r    = lane >> 2;
    const int c    = lane & 3;
    const int g    = lane >> 3, lr = lane & 7;

    float4 acc[4][4];
    #pragma unroll
    for (int i = 0; i < 4; i++)
        #pragma unroll
        for (int j = 0; j < 4; j++) acc[i][j] = make_float4(0.f, 0.f, 0.f, 0.f);

    const uint32_t sbase = smem_u32(dyn);
    const uint32_t fullb = sbase + MBOFF;            // 4 x 8B
    const uint32_t mtyb  = sbase + MBOFF + 32;       // 4 x 8B
    const int T = K >> 5;
    const char* Asrc = (const char*)Apk + (size_t)(m0 >> 7) * T * PKB;
    const char* Bsrc = (const char*)Bpk + (size_t)(n0 >> 7) * T * PKB;

    const uint32_t aoff = (uint32_t)((wm + (g & 1) * 8 + lr) * GP + (g >> 1) * 16);
    const uint32_t boff = (uint32_t)((wn + ((g >> 1) & 1) * 8 + lr) * GP + (g & 1) * 16);

    if (tid == 0) {
        #pragma unroll
        for (int i = 0; i < GNS; i++) { MBAR_INIT(fullb + i * 8, 1); MBAR_INIT(mtyb + i * 8, 8); }
        FENCE_ASYNC();
    }
    __syncthreads();
    if (tid == 0) {
        #pragma unroll
        for (int p = 0; p < 3; p++) {
            MBAR_EXPECT(fullb + p * 8, GSTG);
            CPBULK(sbase + p * GSTG,       Asrc + (size_t)p * PKB, PKB, fullb + p * 8);
            CPBULK(sbase + p * GSTG + PKB, Bsrc + (size_t)p * PKB, PKB, fullb + p * 8);
        }
    }

    for (int t = 0; t < T; t++) {
        const int s = t & 3;
        if (tid == 0 && t + 3 < T) {
            const int u = t + 3, l = u & 3;
            if (u >= GNS) MBAR_WAIT(mtyb + l * 8, (uint32_t)(((u >> 2) - 1) & 1));
            MBAR_EXPECT(fullb + l * 8, GSTG);
            CPBULK(sbase + l * GSTG,       Asrc + (size_t)u * PKB, PKB, fullb + l * 8);
            CPBULK(sbase + l * GSTG + PKB, Bsrc + (size_t)u * PKB, PKB, fullb + l * 8);
        }
        MBAR_WAIT(fullb + s * 8, (uint32_t)((t >> 2) & 1));

        const uint32_t sAb = sbase + s * GSTG;
        const uint32_t sBb = sAb + PKB;
        #pragma unroll
        for (int kg = 0; kg < 2; kg++) {
            uint32_t af[4][4];
            #pragma unroll
            for (int mt = 0; mt < 4; mt++)
                LDSM4(af[mt][0], af[mt][1], af[mt][2], af[mt][3],
                      sAb + aoff + (uint32_t)(mt * 16 * GP + kg * 32));
            uint32_t bf[2][4];
            #pragma unroll
            for (int nt2 = 0; nt2 < 2; nt2++)
                LDSM4(bf[nt2][0], bf[nt2][1], bf[nt2][2], bf[nt2][3],
                      sBb + boff + (uint32_t)(nt2 * 16 * GP + kg * 32));
            #pragma unroll
            for (int mt = 0; mt < 4; mt++) {
                #pragma unroll
                for (int nt2 = 0; nt2 < 2; nt2++) {
                    mma16(acc[mt][nt2 * 2],     af[mt][0], af[mt][1], af[mt][2], af[mt][3],
                          bf[nt2][0], bf[nt2][1]);
                    mma16(acc[mt][nt2 * 2 + 1], af[mt][0], af[mt][1], af[mt][2], af[mt][3],
                          bf[nt2][2], bf[nt2][3]);
                }
            }
        }
        if (lane == 0) MBAR_ARRIVE(mtyb + s * 8);
    }

    #pragma unroll
    for (int mt = 0; mt < 4; mt++) {
        #pragma unroll
        for (int nt = 0; nt < 4; nt++) {
            const int m = m0 + wm + mt * 16 + r;
            const int n = n0 + wn + nt * 8 + c * 2;
            const float2 bv = *(const float2*)&bias[n];
            float2 lo, hi;
            lo.x = acc[mt][nt].x + bv.x;  lo.y = acc[mt][nt].y + bv.y;
            hi.x = acc[mt][nt].z + bv.x;  hi.y = acc[mt][nt].w + bv.y;
            if (MODE == 2) {
                const float2 r0 = *(const float2*)&res[(size_t)m * N + n];
                const float2 r1 = *(const float2*)&res[(size_t)(m + 8) * N + n];
                lo.x += r0.x; lo.y += r0.y;
                hi.x += r1.x; hi.y += r1.y;
            }
            if (MODE == 1) {
                const int which = n >> 9;
                const int nn = n & 511;
                const int hh = nn >> 6, d = nn & 63;
                const int b0i = m >> 11, s0 = m & (Ss - 1);
                const int b1i = (m + 8) >> 11, s1 = (m + 8) & (Ss - 1);
                if (which == 0) {
                    *(__half2*)&C16[((((size_t)b0i * Hh + hh) * Ss) + s0) * DKk + d] =
                        __floats2half2_rn(lo.x, lo.y);
                    *(__half2*)&C16[((((size_t)b1i * Hh + hh) * Ss) + s1) * DKk + d] =
                        __floats2half2_rn(hi.x, hi.y);
                } else {
                    __half* dst = (which == 1) ? Kpk : Vpk;
                    const size_t o0 = ((size_t)(b0i * Hh + hh) * 32 + (s0 >> 6)) * KVBLOB
                                    + (s0 & 63) * KVP + d;
                    const size_t o1 = ((size_t)(b1i * Hh + hh) * 32 + (s1 >> 6)) * KVBLOB
                                    + (s1 & 63) * KVP + d;
                    *(__half2*)&dst[o0] = __floats2half2_rn(lo.x, lo.y);
                    *(__half2*)&dst[o1] = __floats2half2_rn(hi.x, hi.y);
                }
            } else if (MODE == 0) {
                const int kt = N >> 5;
                *(__half2*)&C16[pk_off(m,     n, kt)] = __floats2half2_rn(lo.x, lo.y);
                *(__half2*)&C16[pk_off(m + 8, n, kt)] = __floats2half2_rn(hi.x, hi.y);
            } else {
                *(float2*)&C[(size_t)m * N + n]       = lo;
                *(float2*)&C[(size_t)(m + 8) * N + n] = hi;
            }
        }
    }
}

// ---------------- MMA flash attention (R14: ex2.f16x2, ones-MMA, 3-stage) ------------
__global__ __launch_bounds__(256, 2) void attn_mma(const __half* __restrict__ qh,
                                                   const __half* __restrict__ kpk,
                                                   const __half* __restrict__ vpk,
                                                   const float* __restrict__ hin,
                                                   float* __restrict__ out)
{
    extern __shared__ __align__(16) char dyn[];

    const int bx  = blockIdx.x;
    const int bh  = bx >> 4;
    const int cs  = c_chunk_order[bx & 15] * 128;
    const int tid = threadIdx.x;
    const int w = tid >> 5, lane = tid & 31;
    const int r = lane >> 2;
    const int c = lane & 3;
    const size_t bhS = (size_t)bh * Ss;

    uint32_t qf[4][4];
    {
        const int q0 = cs + w * 16;
        const __half2 scl = __half2half2(__float2half(0.125f * 1.44269504f));
        #pragma unroll
        for (int ks = 0; ks < 4; ks++) {
            const __half* qp0 = qh + (bhS + q0 + r) * DKk + ks * 16 + c * 2;
            const __half* qp1 = qp0 + 8 * DKk;
            __half2 a0 = __hmul2(*(const __half2*)qp0, scl);
            __half2 a1 = __hmul2(*(const __half2*)qp1, scl);
            __half2 a2 = __hmul2(*(const __half2*)(qp0 + 8), scl);
            __half2 a3 = __hmul2(*(const __half2*)(qp1 + 8), scl);
            qf[ks][0] = *(uint32_t*)&a0; qf[ks][1] = *(uint32_t*)&a1;
            qf[ks][2] = *(uint32_t*)&a2; qf[ks][3] = *(uint32_t*)&a3;
        }
    }

    const uint32_t sbase = smem_u32(dyn);
    const uint32_t fullb = sbase + AMBOFF;
    const uint32_t mtyb  = sbase + AMBOFF + 24;

    int w0 = cs - 512; if (w0 < 0) w0 = 0;
    int w1 = cs + 256; if (w1 > Ss) w1 = Ss;
    const int T = (w1 - w0) >> 6;
    const int t0 = w0 >> 6;
    const char* Kb = (const char*)(kpk + (size_t)bh * 32 * KVBLOB);
    const char* Vb = (const char*)(vpk + (size_t)bh * 32 * KVBLOB);

    if (tid == 0) {
        MBAR_INIT(fullb, 1); MBAR_INIT(fullb + 8, 1); MBAR_INIT(fullb + 16, 1);
        MBAR_INIT(mtyb, 8);  MBAR_INIT(mtyb + 8, 8);  MBAR_INIT(mtyb + 16, 8);
        FENCE_ASYNC();
    }
    __syncthreads();
    if (tid == 0) {
        #pragma unroll
        for (int p = 0; p < 2; p++) {
            if (p < T) {
                MBAR_EXPECT(fullb + p * 8, ASTGB);
                CPBULK(sbase + p * ASTGB,        Kb + (size_t)(t0 + p) * KSTG, KSTG, fullb + p * 8);
                CPBULK(sbase + p * ASTGB + KSTG, Vb + (size_t)(t0 + p) * KSTG, KSTG, fullb + p * 8);
            }
        }
    }

    float4 lacc = make_float4(0.f, 0.f, 0.f, 0.f);
    float4 accO[8];
    #pragma unroll
    for (int i = 0; i < 8; i++) accO[i] = make_float4(0.f, 0.f, 0.f, 0.f);

    const int qk_row = (lane & 7) + ((lane >> 4) & 1) * 8;
    const int qk_col = ((lane >> 3) & 1) * 8;
    const int pv_row = (lane & 7) + ((lane >> 3) & 1) * 8;
    const int pv_col = ((lane >> 4) & 1) * 8;

    for (int t = 0; t < T; t++) {
        const int s = t % 3;
        if (tid == 0 && t + 2 < T) {
            const int u = t + 2, l = u % 3;
            if (u >= 3) MBAR_WAIT(mtyb + l * 8, (uint32_t)((u / 3 - 1) & 1));
            MBAR_EXPECT(fullb + l * 8, ASTGB);
            CPBULK(sbase + l * ASTGB,        Kb + (size_t)(t0 + u) * KSTG, KSTG, fullb + l * 8);
            CPBULK(sbase + l * ASTGB + KSTG, Vb + (size_t)(t0 + u) * KSTG, KSTG, fullb + l * 8);
        }
        MBAR_WAIT(fullb + s * 8, (uint32_t)((t / 3) & 1));

        const uint32_t sKb = sbase + s * ASTGB;
        const uint32_t sVb = sKb + KSTG;

        float4 sc[8];
        #pragma unroll
        for (int i = 0; i < 8; i++) sc[i] = make_float4(0.f, 0.f, 0.f, 0.f);
        #pragma unroll
        for (int ks = 0; ks < 4; ks++) {
            #pragma unroll
            for (int n2 = 0; n2 < 4; n2++) {
                uint32_t b0, b1, b2, b3;
                const uint32_t a = sKb +
                    (uint32_t)((n2 * 16 + qk_row) * KVP + ks * 16 + qk_col) * 2;
                LDSM4(b0, b1, b2, b3, a);
                mma16(sc[2 * n2],     qf[ks][0], qf[ks][1], qf[ks][2], qf[ks][3], b0, b1);
                mma16(sc[2 * n2 + 1], qf[ks][0], qf[ks][1], qf[ks][2], qf[ks][3], b2, b3);
            }
        }

        uint32_t pf[4][4];
        #pragma unroll
        for (int ks = 0; ks < 4; ks++) {
            __half2 h;
            uint32_t u0, u1, u2, u3;
            h = __floats2half2_rn(sc[2 * ks].x,     sc[2 * ks].y);     u0 = *(uint32_t*)&h;
            h = __floats2half2_rn(sc[2 * ks].z,     sc[2 * ks].w);     u1 = *(uint32_t*)&h;
            h = __floats2half2_rn(sc[2 * ks + 1].x, sc[2 * ks + 1].y); u2 = *(uint32_t*)&h;
            h = __floats2half2_rn(sc[2 * ks + 1].z, sc[2 * ks + 1].w); u3 = *(uint32_t*)&h;
            EX2H2(pf[ks][0], u0);
            EX2H2(pf[ks][1], u1);
            EX2H2(pf[ks][2], u2);
            EX2H2(pf[ks][3], u3);
        }

        #pragma unroll
        for (int ks = 0; ks < 4; ks++)
            mma16(lacc, pf[ks][0], pf[ks][1], pf[ks][2], pf[ks][3], ONESF, ONESF);

        #pragma unroll
        for (int ks = 0; ks < 4; ks++) {
            #pragma unroll
            for (int d2 = 0; d2 < 4; d2++) {
                uint32_t b0, b1, b2, b3;
                const uint32_t a = sVb +
                    (uint32_t)((ks * 16 + pv_row) * KVP + d2 * 16 + pv_col) * 2;
                LDSM4T(b0, b1, b2, b3, a);
                mma16(accO[2 * d2],     pf[ks][0], pf[ks][1], pf[ks][2], pf[ks][3], b0, b1);
                mma16(accO[2 * d2 + 1], pf[ks][0], pf[ks][1], pf[ks][2], pf[ks][3], b2, b3);
            }
        }
        if (lane == 0) MBAR_ARRIVE(mtyb + s * 8);
    }

    const float inv0 = 1.0f / lacc.x;
    const float inv1 = 1.0f / lacc.z;
    const int b = bh >> 3, head = bh & 7;
    const int q0 = cs + w * 16;
    const size_t base0 = ((size_t)b * Ss + q0 + r) * Dd + head * DKk;
    const size_t base1 = base0 + 8 * Dd;
    #pragma unroll
    for (int dn = 0; dn < 8; dn++) {
        const int d = dn * 8 + c * 2;
        const float2 h0 = *(const float2*)&hin[base0 + d];
        const float2 h1 = *(const float2*)&hin[base1 + d];
        float2 o0, o1;
        o0.x = accO[dn].x * inv0 + h0.x;  o0.y = accO[dn].y * inv0 + h0.y;
        o1.x = accO[dn].z * inv1 + h1.x;  o1.y = accO[dn].w * inv1 + h1.y;
        *(float2*)&out[base0 + d] = o0;
        *(float2*)&out[base1 + d] = o1;
    }
}

// ---------------- launch --------------------------------------------------------------
extern "C" void kernel_launch(void* const* d_in, const int* in_sizes, int n_in,
                              void* d_out, int out_size)
{
    const float* x       = (const float*)d_in[0];
    const float* ln_in_g = (const float*)d_in[2];
    const float* ln_in_b = (const float*)d_in[3];
    const float* wq = (const float*)d_in[4];  const float* bq = (const float*)d_in[5];
    const float* wk = (const float*)d_in[6];  const float* bk = (const float*)d_in[7];
    const float* wv = (const float*)d_in[8];  const float* bv = (const float*)d_in[9];
    const float* ln1_g = (const float*)d_in[10]; const float* ln1_b = (const float*)d_in[11];
    const float* w1 = (const float*)d_in[12]; const float* b1 = (const float*)d_in[13];
    const float* w2 = (const float*)d_in[14]; const float* b2 = (const float*)d_in[15];
    const float* ln2_g = (const float*)d_in[16]; const float* ln2_b = (const float*)d_in[17];
    float* out = (float*)d_out;

    float *ph, *pattn, *pr, *pbqkv;
    __half *ph16, *pq16, *pkpk, *pvpk, *po16, *pf16, *pwqkv, *pw1, *pw2;
    cudaGetSymbolAddress((void**)&ph,     g_h);
    cudaGetSymbolAddress((void**)&ph16,   g_h16pk);
    cudaGetSymbolAddress((void**)&pq16,   g_q16);
    cudaGetSymbolAddress((void**)&pkpk,   g_kpk);
    cudaGetSymbolAddress((void**)&pvpk,   g_vpk);
    cudaGetSymbolAddress((void**)&pattn,  g_attn);
    cudaGetSymbolAddress((void**)&po16,   g_o16pk);
    cudaGetSymbolAddress((void**)&pf16,   g_f16pk);
    cudaGetSymbolAddress((void**)&pr,     g_r);
    cudaGetSymbolAddress((void**)&pwqkv,  g_wqkvpk);
    cudaGetSymbolAddress((void**)&pw1,    g_w1pk);
    cudaGetSymbolAddress((void**)&pw2,    g_w2pk);
    cudaGetSymbolAddress((void**)&pbqkv,  g_bqkv);

    cudaFuncSetAttribute(mma_gemm<0>, cudaFuncAttributeMaxDynamicSharedMemorySize, GEMM_SMEM);
    cudaFuncSetAttribute(mma_gemm<1>, cudaFuncAttributeMaxDynamicSharedMemorySize, GEMM_SMEM);
    cudaFuncSetAttribute(mma_gemm<2>, cudaFuncAttributeMaxDynamicSharedMemorySize, GEMM_SMEM);
    cudaFuncSetAttribute(attn_mma,    cudaFuncAttributeMaxDynamicSharedMemorySize, ATTN_SMEM);

    // 0. merged prep -> packed weights
    prep_kernel<<<2822, 256>>>(wq, wk, wv, w1, w2, bq, bk, bv,
                               pwqkv, pw1, pw2, pbqkv);

    // 1. h = LN(x)
    ln_kernel<<<ROWS / 2, 256>>>(x, ln_in_g, ln_in_b, ph, ph16);

    // 2. fused QKV: Q normal layout, K/V packed blobs
    mma_gemm<1><<<dim3(12, 64), 256, GEMM_SMEM>>>(ph16, pwqkv, pbqkv, nullptr, nullptr,
                                                  pq16, pkpk, pvpk, ROWS, 3 * Dd, Dd);

    // 3. attention (heavy-first 1D grid) + residual h
    attn_mma<<<512, 256, ATTN_SMEM>>>(pq16, pkpk, pvpk, ph, pattn);

    // 4. LN1 -> packed fp16
    ln_kernel<<<ROWS / 2, 256>>>(pattn, ln1_g, ln1_b, nullptr, po16);

    // 5. FFN
    mma_gemm<0><<<dim3(FFNf / 128, 64), 256, GEMM_SMEM>>>(po16, pw1, b1, nullptr, nullptr,
                                                          pf16, nullptr, nullptr, ROWS, FFNf, Dd);
    mma_gemm<2><<<dim3(Dd / 128, 64), 256, GEMM_SMEM>>>(pf16, pw2, b2, pattn, pr, nullptr,
                                                        nullptr, nullptr, ROWS, Dd, FFNf);

    // 6. out = LN2
    ln_kernel<<<ROWS / 2, 256>>>(pr, ln2_g, ln2_b, out, nullptr);
}